// round 1
// baseline (speedup 1.0000x reference)
#include <cuda_runtime.h>
#include <math.h>

#define DIM 2048
#define NH  16
#define HD  128
#define B2  2
#define T2  2048
#define BT  4096   // B*T
#define BH  32     // B*NH

// ---------------- device scratch (no allocation allowed) ----------------
__device__ float g_Wq[DIM*DIM];
__device__ float g_Wk[DIM*DIM];
__device__ float g_Wv[DIM*DIM];
__device__ float g_Wo[DIM*DIM];
__device__ float g_Qa[BH*T2*HD];   // [BH][T][HD] post-projection
__device__ float g_Ka[BH*T2*HD];
__device__ float g_Vb[BH*T2*HD];
__device__ float g_Qt[BH*HD*T2];   // [BH][HD][T] post-RoPE (transposed)
__device__ float g_Kt[BH*HD*T2];
__device__ float g_Yb[BH*T2*HD];   // attention out [BH][T][HD]
__device__ float g_Y2[BT*DIM];     // attention out [BT][DIM]

// ---------------- ternary dequant ----------------
// w: [2048 rows][2048], 16 groups of 128 per row.
// scale = max(mean(|w_group|), 1e-8); q in {-1,0,1}; out = q*scale.
__global__ void __launch_bounds__(256) dequant_kernel(
    const float* __restrict__ w, float* __restrict__ o)
{
    int row = blockIdx.x;
    int tid = threadIdx.x;                 // 256 threads, 8 elems each; 16 threads/group
    const float* wr = w + (size_t)row*DIM + tid*8;
    float v[8]; float s = 0.f;
    #pragma unroll
    for (int i=0;i<8;i++){ v[i]=wr[i]; s += fabsf(v[i]); }
    #pragma unroll
    for (int off=8; off; off>>=1)
        s += __shfl_xor_sync(0xffffffffu, s, off, 16);
    float scale = fmaxf(s*(1.0f/128.0f), 1e-8f);
    float inv = 1.0f/scale;
    float* orow = o + (size_t)row*DIM + tid*8;
    #pragma unroll
    for (int i=0;i<8;i++){
        float wn = v[i]*inv;
        float q = (wn > 0.5f) ? 1.0f : ((wn < -0.5f) ? -1.0f : 0.0f);
        orow[i] = q*scale;
    }
}

// ---------------- fp32 SGEMM: C[m,n] = sum_k A[m,k]*B[n,k] ----------------
// 128x128 tile, BK=8, 8x8 per thread, 256 threads.
// mode 0: C row-major [M][N].  mode 1: scatter to [B][H][T][HD] layout.
__global__ void __launch_bounds__(256) gemm_kernel(
    const float* __restrict__ A, const float* __restrict__ Bw,
    float* __restrict__ C, int M, int N, int K, int mode)
{
    __shared__ float As[8][128];
    __shared__ float Bs[8][128];
    int tid = threadIdx.x;
    int bm = blockIdx.y, bn = blockIdx.x;
    int lr = tid >> 1;
    int lc = (tid & 1) << 2;
    const float* Ag = A  + ((size_t)(bm*128 + lr))*K + lc;
    const float* Bg = Bw + ((size_t)(bn*128 + lr))*K + lc;
    int tx = tid & 15, ty = tid >> 4;
    float acc[8][8];
    #pragma unroll
    for (int i=0;i<8;i++)
        #pragma unroll
        for (int j=0;j<8;j++) acc[i][j]=0.f;

    for (int k0=0; k0<K; k0+=8){
        float4 av = *(const float4*)(Ag + k0);
        float4 bv = *(const float4*)(Bg + k0);
        __syncthreads();
        As[lc+0][lr]=av.x; As[lc+1][lr]=av.y; As[lc+2][lr]=av.z; As[lc+3][lr]=av.w;
        Bs[lc+0][lr]=bv.x; Bs[lc+1][lr]=bv.y; Bs[lc+2][lr]=bv.z; Bs[lc+3][lr]=bv.w;
        __syncthreads();
        #pragma unroll
        for (int k=0;k<8;k++){
            float a[8], b[8];
            *(float4*)(a)   = *(const float4*)&As[k][ty*8];
            *(float4*)(a+4) = *(const float4*)&As[k][ty*8+4];
            *(float4*)(b)   = *(const float4*)&Bs[k][tx*8];
            *(float4*)(b+4) = *(const float4*)&Bs[k][tx*8+4];
            #pragma unroll
            for (int i=0;i<8;i++)
                #pragma unroll
                for (int j=0;j<8;j++) acc[i][j] = fmaf(a[i], b[j], acc[i][j]);
        }
    }

    if (mode == 0){
        #pragma unroll
        for (int i=0;i<8;i++){
            int row = bm*128 + ty*8 + i;
            float* cp = C + (size_t)row*N + bn*128 + tx*8;
            *(float4*)cp     = make_float4(acc[i][0],acc[i][1],acc[i][2],acc[i][3]);
            *(float4*)(cp+4) = make_float4(acc[i][4],acc[i][5],acc[i][6],acc[i][7]);
        }
    } else {
        #pragma unroll
        for (int i=0;i<8;i++){
            int m  = bm*128 + ty*8 + i;
            int b_ = m >> 11, t = m & 2047;
            int n0 = bn*128 + tx*8;
            int h  = n0 >> 7, d = n0 & 127;
            float* cp = C + ((size_t)((b_*NH + h)*T2 + t))*HD + d;
            *(float4*)cp     = make_float4(acc[i][0],acc[i][1],acc[i][2],acc[i][3]);
            *(float4*)(cp+4) = make_float4(acc[i][4],acc[i][5],acc[i][6],acc[i][7]);
        }
    }
}

// ---------------- RoPE + transpose: [BH][T][HD] -> [BH][HD][T] ----------------
__global__ void __launch_bounds__(256) rope_kernel(
    const float* __restrict__ in, float* __restrict__ out)
{
    __shared__ float S[128][65];
    int bh  = blockIdx.y;
    int t0  = blockIdx.x * 64;
    int tid = threadIdx.x;
    #pragma unroll
    for (int k=0;k<16;k++){
        int e  = tid + k*256;        // 64 t x 64 pairs
        int tl = e >> 6, j = e & 63;
        const float* p = in + ((size_t)bh*T2 + t0 + tl)*HD;
        float x1 = p[j], x2 = p[j+64];
        float invf = exp2f(-(float)j * (13.287712379549449f/64.0f)); // 10000^(-j/64)
        float ang  = (float)(t0+tl) * invf;
        float sn, cs; sincosf(ang, &sn, &cs);
        S[j][tl]    = x1*cs - x2*sn;
        S[j+64][tl] = x1*sn + x2*cs;
    }
    __syncthreads();
    #pragma unroll
    for (int k=0;k<32;k++){
        int e = tid + k*256;         // 128 d x 64 t
        int d = e >> 6, tl = e & 63;
        out[((size_t)bh*HD + d)*T2 + t0 + tl] = S[d][tl];
    }
}

// ---------------- flash attention (fp32, causal) ----------------
// Qt,Kt: [BH][HD][T]; V: [BH][T][HD]; Ob: [BH][T][HD]
// BM=64 queries/block, BN=64 keys/step. 256 threads: tx(0..15) x ty(0..15).
// S tile: 4x4 per thread. O tile: 4 rows x 8 dims per thread.
#define FQS 68
#define FVS 132
#define FPS 68
#define FLASH_SMEM ((128*FQS*2 + 64*FVS + 64*FPS)*4)

__global__ void __launch_bounds__(256) flash_kernel(
    const float* __restrict__ Qt, const float* __restrict__ Kt,
    const float* __restrict__ V,  float* __restrict__ Ob)
{
    extern __shared__ float sm[];
    float* Qs = sm;                  // [128][FQS]  (d-major)
    float* Ks = Qs + 128*FQS;        // [128][FQS]  (d-major)
    float* Vs = Ks + 128*FQS;        // [64][FVS]   (n-major)
    float* Ps = Vs + 64*FVS;         // [64][FPS]   (n-major: Ps[n][m])

    int qb  = blockIdx.x;
    int bh  = blockIdx.y;
    int tid = threadIdx.x;
    int tx  = tid & 15, ty = tid >> 4;

    const float* qbase = Qt + (size_t)bh*HD*T2 + qb*64;
    #pragma unroll
    for (int k=0;k<32;k++){
        int e = tid + k*256;
        int d = e >> 6, ml = e & 63;
        Qs[d*FQS + ml] = qbase[(size_t)d*T2 + ml];
    }

    float m_i[4], l_i[4], acc[4][8];
    #pragma unroll
    for (int i=0;i<4;i++){
        m_i[i] = -1e30f; l_i[i] = 0.f;
        #pragma unroll
        for (int j=0;j<8;j++) acc[i][j]=0.f;
    }

    const float* kbase = Kt + (size_t)bh*HD*T2;
    const float* vbase = V  + (size_t)bh*T2*HD;
    const float scale = 0.08838834764831845f;   // 1/sqrt(128)

    for (int kb=0; kb<=qb; kb++){
        __syncthreads();  // prior PV done before overwriting Ks/Vs
        #pragma unroll
        for (int k=0;k<32;k++){
            int e = tid + k*256;
            int d = e >> 6, nl = e & 63;
            Ks[d*FQS + nl] = kbase[(size_t)d*T2 + kb*64 + nl];
        }
        #pragma unroll
        for (int k=0;k<32;k++){
            int e = tid + k*256;
            int n = e >> 7, d = e & 127;
            Vs[n*FVS + d] = vbase[(size_t)(kb*64+n)*HD + d];
        }
        __syncthreads();

        // S = Q K^T (64x64), micro 4x4
        float s[4][4];
        #pragma unroll
        for (int i=0;i<4;i++)
            #pragma unroll
            for (int j=0;j<4;j++) s[i][j]=0.f;
        for (int d=0; d<128; d++){
            float a[4], b[4];
            *(float4*)a = *(const float4*)&Qs[d*FQS + ty*4];
            *(float4*)b = *(const float4*)&Ks[d*FQS + tx*4];
            #pragma unroll
            for (int i=0;i<4;i++)
                #pragma unroll
                for (int j=0;j<4;j++) s[i][j] = fmaf(a[i], b[j], s[i][j]);
        }

        bool diag = (kb == qb);
        #pragma unroll
        for (int i=0;i<4;i++){
            float mx = -1e30f;
            #pragma unroll
            for (int j=0;j<4;j++){
                float v = s[i][j]*scale;
                if (diag && (tx*4+j > ty*4+i)) v = -1e30f;   // causal mask
                s[i][j]=v;
                mx = fmaxf(mx, v);
            }
            #pragma unroll
            for (int off=8; off; off>>=1)
                mx = fmaxf(mx, __shfl_xor_sync(0xffffffffu, mx, off, 16));
            float newm = fmaxf(m_i[i], mx);
            float al   = __expf(m_i[i]-newm);
            m_i[i] = newm;
            float p[4]; float ps=0.f;
            #pragma unroll
            for (int j=0;j<4;j++){ p[j]=__expf(s[i][j]-newm); ps+=p[j]; }
            #pragma unroll
            for (int off=8; off; off>>=1)
                ps += __shfl_xor_sync(0xffffffffu, ps, off, 16);
            l_i[i] = l_i[i]*al + ps;
            #pragma unroll
            for (int j=0;j<8;j++) acc[i][j]*=al;
            #pragma unroll
            for (int j=0;j<4;j++)
                Ps[(tx*4+j)*FPS + ty*4 + i] = p[j];          // store transposed
        }
        __syncthreads();

        // O += P V  (64x128, K-dim = 64 keys), micro 4x8
        for (int n=0;n<64;n++){
            float a[4], b[8];
            *(float4*)a     = *(const float4*)&Ps[n*FPS + ty*4];
            *(float4*)b     = *(const float4*)&Vs[n*FVS + tx*8];
            *(float4*)(b+4) = *(const float4*)&Vs[n*FVS + tx*8 + 4];
            #pragma unroll
            for (int i=0;i<4;i++)
                #pragma unroll
                for (int j=0;j<8;j++) acc[i][j] = fmaf(a[i], b[j], acc[i][j]);
        }
    }

    float* obase = Ob + ((size_t)bh*T2 + qb*64)*HD;
    #pragma unroll
    for (int i=0;i<4;i++){
        float inv = 1.0f / l_i[i];
        float* cp = obase + (size_t)(ty*4+i)*HD + tx*8;
        *(float4*)cp     = make_float4(acc[i][0]*inv, acc[i][1]*inv,
                                       acc[i][2]*inv, acc[i][3]*inv);
        *(float4*)(cp+4) = make_float4(acc[i][4]*inv, acc[i][5]*inv,
                                       acc[i][6]*inv, acc[i][7]*inv);
    }
}

// ---------------- [BH][T][HD] -> [BT][DIM] ----------------
__global__ void __launch_bounds__(256) transpose_kernel(
    const float* __restrict__ Yb, float* __restrict__ Y2)
{
    size_t i = (size_t)blockIdx.x*256 + threadIdx.x;
    int d = (int)(i & 127);
    size_t r = i >> 7;
    int t = (int)(r & 2047);
    size_t r2 = r >> 11;
    int h = (int)(r2 & 15);
    int b = (int)(r2 >> 4);
    Y2[((size_t)(b*T2 + t))*DIM + h*HD + d] = Yb[i];
}

// ---------------- launch ----------------
extern "C" void kernel_launch(void* const* d_in, const int* in_sizes, int n_in,
                              void* d_out, int out_size)
{
    const float* x  = (const float*)d_in[0];
    const float* wq = (const float*)d_in[1];
    const float* wk = (const float*)d_in[2];
    const float* wv = (const float*)d_in[3];
    const float* wo = (const float*)d_in[4];
    float* out = (float*)d_out;

    float *Wq,*Wk,*Wv,*Wo,*Qa,*Ka,*Vb,*Qt,*Kt,*Yb,*Y2;
    cudaGetSymbolAddress((void**)&Wq, g_Wq);
    cudaGetSymbolAddress((void**)&Wk, g_Wk);
    cudaGetSymbolAddress((void**)&Wv, g_Wv);
    cudaGetSymbolAddress((void**)&Wo, g_Wo);
    cudaGetSymbolAddress((void**)&Qa, g_Qa);
    cudaGetSymbolAddress((void**)&Ka, g_Ka);
    cudaGetSymbolAddress((void**)&Vb, g_Vb);
    cudaGetSymbolAddress((void**)&Qt, g_Qt);
    cudaGetSymbolAddress((void**)&Kt, g_Kt);
    cudaGetSymbolAddress((void**)&Yb, g_Yb);
    cudaGetSymbolAddress((void**)&Y2, g_Y2);

    cudaFuncSetAttribute(flash_kernel,
        cudaFuncAttributeMaxDynamicSharedMemorySize, FLASH_SMEM);

    dequant_kernel<<<DIM,256>>>(wq, Wq);
    dequant_kernel<<<DIM,256>>>(wk, Wk);
    dequant_kernel<<<DIM,256>>>(wv, Wv);
    dequant_kernel<<<DIM,256>>>(wo, Wo);

    dim3 gg(DIM/128, BT/128);
    gemm_kernel<<<gg,256>>>(x, Wq, Qa, BT, DIM, DIM, 1);
    gemm_kernel<<<gg,256>>>(x, Wk, Ka, BT, DIM, DIM, 1);
    gemm_kernel<<<gg,256>>>(x, Wv, Vb, BT, DIM, DIM, 1);

    rope_kernel<<<dim3(T2/64, BH),256>>>(Qa, Qt);
    rope_kernel<<<dim3(T2/64, BH),256>>>(Ka, Kt);

    flash_kernel<<<dim3(T2/64, BH),256, FLASH_SMEM>>>(Qt, Kt, Vb, Yb);

    transpose_kernel<<<(BT*DIM)/256, 256>>>(Yb, Y2);

    gemm_kernel<<<gg,256>>>(Y2, Wo, out, BT, DIM, DIM, 0);
}

// round 2
// speedup vs baseline: 2.0970x; 2.0970x over previous
#include <cuda_runtime.h>
#include <math.h>

#define DIM 2048
#define NH  16
#define HD  128
#define B2  2
#define T2  2048
#define BT  4096   // B*T
#define BH  32     // B*NH

// ---------------- device scratch (no allocation allowed) ----------------
__device__ float g_Wq[DIM*DIM];
__device__ float g_Wk[DIM*DIM];
__device__ float g_Wv[DIM*DIM];
__device__ float g_Wo[DIM*DIM];
__device__ float g_Qa[BH*T2*HD];   // [BH][T][HD] post-projection
__device__ float g_Ka[BH*T2*HD];
__device__ float g_Vb[BH*T2*HD];
__device__ float g_Qt[BH*HD*T2];   // [BH][HD][T] post-RoPE (transposed)
__device__ float g_Kt[BH*HD*T2];
__device__ float g_Yb[BH*T2*HD];   // attention out [BH][T][HD]
__device__ float g_Y2[BT*DIM];     // attention out [BT][DIM]

// ---------------- mma helpers ----------------
__device__ __forceinline__ unsigned f2tf(float x){
    unsigned r; asm("cvt.rna.tf32.f32 %0, %1;" : "=r"(r) : "f"(x)); return r;
}
__device__ __forceinline__ void mma8(float* d, const unsigned* a, const unsigned* b){
    asm volatile("mma.sync.aligned.m16n8k8.row.col.f32.tf32.tf32.f32 "
                 "{%0,%1,%2,%3},{%4,%5,%6,%7},{%8,%9},{%0,%1,%2,%3};"
                 : "+f"(d[0]),"+f"(d[1]),"+f"(d[2]),"+f"(d[3])
                 : "r"(a[0]),"r"(a[1]),"r"(a[2]),"r"(a[3]),"r"(b[0]),"r"(b[1]));
}

// ---------------- ternary dequant ----------------
__global__ void __launch_bounds__(256) dequant_kernel(
    const float* __restrict__ w, float* __restrict__ o)
{
    int row = blockIdx.x;
    int tid = threadIdx.x;                 // 256 threads, 8 elems each; 16 threads/group
    const float* wr = w + (size_t)row*DIM + tid*8;
    float v[8]; float s = 0.f;
    #pragma unroll
    for (int i=0;i<8;i++){ v[i]=wr[i]; s += fabsf(v[i]); }
    #pragma unroll
    for (int off=8; off; off>>=1)
        s += __shfl_xor_sync(0xffffffffu, s, off, 16);
    float scale = fmaxf(s*(1.0f/128.0f), 1e-8f);
    float inv = 1.0f/scale;
    float* orow = o + (size_t)row*DIM + tid*8;
    #pragma unroll
    for (int i=0;i<8;i++){
        float wn = v[i]*inv;
        float q = (wn > 0.5f) ? 1.0f : ((wn < -0.5f) ? -1.0f : 0.0f);
        orow[i] = q*scale;
    }
}

// ---------------- tf32 tensor-core GEMM: C[m,n] = sum_k A[m,k]*B[n,k] ---------
// CTA tile 128x128, BK=32. 256 threads = 8 warps, warp grid 2(m) x 4(n),
// warp tile 64x32 via m16n8k8 tf32 mma. Padded smem (stride 36) ->
// fragment LDS banks (4g+t) mod 32 all distinct => conflict-free.
// mode 0: C row-major [M][N].  mode 1: scatter to [B][H][T][HD].
__global__ void __launch_bounds__(256) gemm_tf32_kernel(
    const float* __restrict__ A, const float* __restrict__ Bw,
    float* __restrict__ C, int M, int N, int K, int mode)
{
    __shared__ unsigned As[128][36];
    __shared__ unsigned Bs[128][36];
    int tid  = threadIdx.x;
    int bm   = blockIdx.y, bn = blockIdx.x;
    int warp = tid>>5, lane = tid&31;
    int wm   = (warp&1)<<6;     // 0 or 64
    int wn   = (warp>>1)<<5;    // 0,32,64,96
    int g    = lane>>2, t = lane&3;

    float acc[4][4][4];
    #pragma unroll
    for(int i=0;i<4;i++)
        #pragma unroll
        for(int j=0;j<4;j++)
            #pragma unroll
            for(int r=0;r<4;r++) acc[i][j][r]=0.f;

    int lr = tid>>3;            // 0..31
    int lk = (tid&7)<<2;        // 0,4,..,28
    const float* Ag = A  + (size_t)(bm*128 + lr)*K + lk;
    const float* Bg = Bw + (size_t)(bn*128 + lr)*K + lk;

    float4 av[4], bv[4];
    #pragma unroll
    for(int i=0;i<4;i++){
        av[i] = *(const float4*)(Ag + (size_t)i*32*K);
        bv[i] = *(const float4*)(Bg + (size_t)i*32*K);
    }

    for(int k0=0; k0<K; k0+=32){
        __syncthreads();
        #pragma unroll
        for(int i=0;i<4;i++){
            As[lr+i*32][lk+0]=f2tf(av[i].x); As[lr+i*32][lk+1]=f2tf(av[i].y);
            As[lr+i*32][lk+2]=f2tf(av[i].z); As[lr+i*32][lk+3]=f2tf(av[i].w);
            Bs[lr+i*32][lk+0]=f2tf(bv[i].x); Bs[lr+i*32][lk+1]=f2tf(bv[i].y);
            Bs[lr+i*32][lk+2]=f2tf(bv[i].z); Bs[lr+i*32][lk+3]=f2tf(bv[i].w);
        }
        __syncthreads();
        if (k0+32 < K){
            #pragma unroll
            for(int i=0;i<4;i++){             // prefetch next tile (hides L2 lat)
                av[i] = *(const float4*)(Ag + k0+32 + (size_t)i*32*K);
                bv[i] = *(const float4*)(Bg + k0+32 + (size_t)i*32*K);
            }
        }
        #pragma unroll
        for(int ks=0;ks<4;ks++){
            int c = ks*8 + t;
            unsigned af[4][4], bf[4][2];
            #pragma unroll
            for(int mi=0;mi<4;mi++){
                int row = wm + mi*16 + g;
                af[mi][0]=As[row  ][c];   af[mi][1]=As[row+8][c];
                af[mi][2]=As[row  ][c+4]; af[mi][3]=As[row+8][c+4];
            }
            #pragma unroll
            for(int ni=0;ni<4;ni++){
                int n = wn + ni*8 + g;
                bf[ni][0]=Bs[n][c]; bf[ni][1]=Bs[n][c+4];
            }
            #pragma unroll
            for(int mi=0;mi<4;mi++)
                #pragma unroll
                for(int ni=0;ni<4;ni++)
                    mma8(acc[mi][ni], af[mi], bf[ni]);
        }
    }

    // epilogue: c0,c1 -> (row g, cols 2t,2t+1); c2,c3 -> (row g+8)
    #pragma unroll
    for(int mi=0;mi<4;mi++){
        #pragma unroll
        for(int ni=0;ni<4;ni++){
            int rowa = bm*128 + wm + mi*16 + g;
            int col  = bn*128 + wn + ni*8 + 2*t;
            if (mode == 0){
                float2* p0 = (float2*)(C + (size_t)rowa*N + col);
                *p0 = make_float2(acc[mi][ni][0], acc[mi][ni][1]);
                float2* p1 = (float2*)(C + (size_t)(rowa+8)*N + col);
                *p1 = make_float2(acc[mi][ni][2], acc[mi][ni][3]);
            } else {
                int h = col>>7, d = col&127;
                int m0 = rowa;
                int b0_=m0>>11, t0_=m0&2047;
                float2* p0 = (float2*)(C + ((size_t)((b0_*NH+h)*T2+t0_))*HD + d);
                *p0 = make_float2(acc[mi][ni][0], acc[mi][ni][1]);
                int m1 = rowa+8;
                int b1_=m1>>11, t1_=m1&2047;
                float2* p1 = (float2*)(C + ((size_t)((b1_*NH+h)*T2+t1_))*HD + d);
                *p1 = make_float2(acc[mi][ni][2], acc[mi][ni][3]);
            }
        }
    }
}

// ---------------- RoPE + transpose: [BH][T][HD] -> [BH][HD][T] ----------------
__global__ void __launch_bounds__(256) rope_kernel(
    const float* __restrict__ in, float* __restrict__ out)
{
    __shared__ float S[128][65];
    int bh  = blockIdx.y;
    int t0  = blockIdx.x * 64;
    int tid = threadIdx.x;
    #pragma unroll
    for (int k=0;k<16;k++){
        int e  = tid + k*256;        // 64 t x 64 pairs
        int tl = e >> 6, j = e & 63;
        const float* p = in + ((size_t)bh*T2 + t0 + tl)*HD;
        float x1 = p[j], x2 = p[j+64];
        float invf = exp2f(-(float)j * (13.287712379549449f/64.0f)); // 10000^(-j/64)
        float ang  = (float)(t0+tl) * invf;
        float sn, cs; sincosf(ang, &sn, &cs);
        S[j][tl]    = x1*cs - x2*sn;
        S[j+64][tl] = x1*sn + x2*cs;
    }
    __syncthreads();
    #pragma unroll
    for (int k=0;k<32;k++){
        int e = tid + k*256;         // 128 d x 64 t
        int d = e >> 6, tl = e & 63;
        out[((size_t)bh*HD + d)*T2 + t0 + tl] = S[d][tl];
    }
}

// ---------------- flash attention (fp32, causal) ----------------
#define FQS 68
#define FVS 132
#define FPS 68
#define FLASH_SMEM ((128*FQS*2 + 64*FVS + 64*FPS)*4)

__global__ void __launch_bounds__(256) flash_kernel(
    const float* __restrict__ Qt, const float* __restrict__ Kt,
    const float* __restrict__ V,  float* __restrict__ Ob)
{
    extern __shared__ float sm[];
    float* Qs = sm;                  // [128][FQS]  (d-major)
    float* Ks = Qs + 128*FQS;        // [128][FQS]  (d-major)
    float* Vs = Ks + 128*FQS;        // [64][FVS]   (n-major)
    float* Ps = Vs + 64*FVS;         // [64][FPS]   (n-major: Ps[n][m])

    int qb  = blockIdx.x;
    int bh  = blockIdx.y;
    int tid = threadIdx.x;
    int tx  = tid & 15, ty = tid >> 4;

    const float* qbase = Qt + (size_t)bh*HD*T2 + qb*64;
    #pragma unroll
    for (int k=0;k<32;k++){
        int e = tid + k*256;
        int d = e >> 6, ml = e & 63;
        Qs[d*FQS + ml] = qbase[(size_t)d*T2 + ml];
    }

    float m_i[4], l_i[4], acc[4][8];
    #pragma unroll
    for (int i=0;i<4;i++){
        m_i[i] = -1e30f; l_i[i] = 0.f;
        #pragma unroll
        for (int j=0;j<8;j++) acc[i][j]=0.f;
    }

    const float* kbase = Kt + (size_t)bh*HD*T2;
    const float* vbase = V  + (size_t)bh*T2*HD;
    const float scale = 0.08838834764831845f;   // 1/sqrt(128)

    for (int kb=0; kb<=qb; kb++){
        __syncthreads();
        #pragma unroll
        for (int k=0;k<32;k++){
            int e = tid + k*256;
            int d = e >> 6, nl = e & 63;
            Ks[d*FQS + nl] = kbase[(size_t)d*T2 + kb*64 + nl];
        }
        #pragma unroll
        for (int k=0;k<32;k++){
            int e = tid + k*256;
            int n = e >> 7, d = e & 127;
            Vs[n*FVS + d] = vbase[(size_t)(kb*64+n)*HD + d];
        }
        __syncthreads();

        float s[4][4];
        #pragma unroll
        for (int i=0;i<4;i++)
            #pragma unroll
            for (int j=0;j<4;j++) s[i][j]=0.f;
        for (int d=0; d<128; d++){
            float a[4], b[4];
            *(float4*)a = *(const float4*)&Qs[d*FQS + ty*4];
            *(float4*)b = *(const float4*)&Ks[d*FQS + tx*4];
            #pragma unroll
            for (int i=0;i<4;i++)
                #pragma unroll
                for (int j=0;j<4;j++) s[i][j] = fmaf(a[i], b[j], s[i][j]);
        }

        bool diag = (kb == qb);
        #pragma unroll
        for (int i=0;i<4;i++){
            float mx = -1e30f;
            #pragma unroll
            for (int j=0;j<4;j++){
                float v = s[i][j]*scale;
                if (diag && (tx*4+j > ty*4+i)) v = -1e30f;
                s[i][j]=v;
                mx = fmaxf(mx, v);
            }
            #pragma unroll
            for (int off=8; off; off>>=1)
                mx = fmaxf(mx, __shfl_xor_sync(0xffffffffu, mx, off, 16));
            float newm = fmaxf(m_i[i], mx);
            float al   = __expf(m_i[i]-newm);
            m_i[i] = newm;
            float p[4]; float ps=0.f;
            #pragma unroll
            for (int j=0;j<4;j++){ p[j]=__expf(s[i][j]-newm); ps+=p[j]; }
            #pragma unroll
            for (int off=8; off; off>>=1)
                ps += __shfl_xor_sync(0xffffffffu, ps, off, 16);
            l_i[i] = l_i[i]*al + ps;
            #pragma unroll
            for (int j=0;j<8;j++) acc[i][j]*=al;
            #pragma unroll
            for (int j=0;j<4;j++)
                Ps[(tx*4+j)*FPS + ty*4 + i] = p[j];
        }
        __syncthreads();

        for (int n=0;n<64;n++){
            float a[4], b[8];
            *(float4*)a     = *(const float4*)&Ps[n*FPS + ty*4];
            *(float4*)b     = *(const float4*)&Vs[n*FVS + tx*8];
            *(float4*)(b+4) = *(const float4*)&Vs[n*FVS + tx*8 + 4];
            #pragma unroll
            for (int i=0;i<4;i++)
                #pragma unroll
                for (int j=0;j<8;j++) acc[i][j] = fmaf(a[i], b[j], acc[i][j]);
        }
    }

    float* obase = Ob + ((size_t)bh*T2 + qb*64)*HD;
    #pragma unroll
    for (int i=0;i<4;i++){
        float inv = 1.0f / l_i[i];
        float* cp = obase + (size_t)(ty*4+i)*HD + tx*8;
        *(float4*)cp     = make_float4(acc[i][0]*inv, acc[i][1]*inv,
                                       acc[i][2]*inv, acc[i][3]*inv);
        *(float4*)(cp+4) = make_float4(acc[i][4]*inv, acc[i][5]*inv,
                                       acc[i][6]*inv, acc[i][7]*inv);
    }
}

// ---------------- [BH][T][HD] -> [BT][DIM] ----------------
__global__ void __launch_bounds__(256) transpose_kernel(
    const float* __restrict__ Yb, float* __restrict__ Y2)
{
    size_t i = (size_t)blockIdx.x*256 + threadIdx.x;
    int d = (int)(i & 127);
    size_t r = i >> 7;
    int t = (int)(r & 2047);
    size_t r2 = r >> 11;
    int h = (int)(r2 & 15);
    int b = (int)(r2 >> 4);
    Y2[((size_t)(b*T2 + t))*DIM + h*HD + d] = Yb[i];
}

// ---------------- launch ----------------
extern "C" void kernel_launch(void* const* d_in, const int* in_sizes, int n_in,
                              void* d_out, int out_size)
{
    const float* x  = (const float*)d_in[0];
    const float* wq = (const float*)d_in[1];
    const float* wk = (const float*)d_in[2];
    const float* wv = (const float*)d_in[3];
    const float* wo = (const float*)d_in[4];
    float* out = (float*)d_out;

    float *Wq,*Wk,*Wv,*Wo,*Qa,*Ka,*Vb,*Qt,*Kt,*Yb,*Y2;
    cudaGetSymbolAddress((void**)&Wq, g_Wq);
    cudaGetSymbolAddress((void**)&Wk, g_Wk);
    cudaGetSymbolAddress((void**)&Wv, g_Wv);
    cudaGetSymbolAddress((void**)&Wo, g_Wo);
    cudaGetSymbolAddress((void**)&Qa, g_Qa);
    cudaGetSymbolAddress((void**)&Ka, g_Ka);
    cudaGetSymbolAddress((void**)&Vb, g_Vb);
    cudaGetSymbolAddress((void**)&Qt, g_Qt);
    cudaGetSymbolAddress((void**)&Kt, g_Kt);
    cudaGetSymbolAddress((void**)&Yb, g_Yb);
    cudaGetSymbolAddress((void**)&Y2, g_Y2);

    cudaFuncSetAttribute(flash_kernel,
        cudaFuncAttributeMaxDynamicSharedMemorySize, FLASH_SMEM);

    dequant_kernel<<<DIM,256>>>(wq, Wq);
    dequant_kernel<<<DIM,256>>>(wk, Wk);
    dequant_kernel<<<DIM,256>>>(wv, Wv);
    dequant_kernel<<<DIM,256>>>(wo, Wo);

    dim3 gg(DIM/128, BT/128);
    gemm_tf32_kernel<<<gg,256>>>(x, Wq, Qa, BT, DIM, DIM, 1);
    gemm_tf32_kernel<<<gg,256>>>(x, Wk, Ka, BT, DIM, DIM, 1);
    gemm_tf32_kernel<<<gg,256>>>(x, Wv, Vb, BT, DIM, DIM, 1);

    rope_kernel<<<dim3(T2/64, BH),256>>>(Qa, Qt);
    rope_kernel<<<dim3(T2/64, BH),256>>>(Ka, Kt);

    flash_kernel<<<dim3(T2/64, BH),256, FLASH_SMEM>>>(Qt, Kt, Vb, Yb);

    transpose_kernel<<<(BT*DIM)/256, 256>>>(Yb, Y2);

    gemm_tf32_kernel<<<gg,256>>>(Y2, Wo, out, BT, DIM, DIM, 0);
}

// round 3
// speedup vs baseline: 3.6479x; 1.7396x over previous
#include <cuda_runtime.h>
#include <math.h>

#define DIM 2048
#define NH  16
#define HD  128
#define B2  2
#define T2  2048
#define BT  4096   // B*T
#define BH  32     // B*NH

// ---------------- device scratch ----------------
__device__ float g_Wq[DIM*DIM];
__device__ float g_Wk[DIM*DIM];
__device__ float g_Wv[DIM*DIM];
__device__ float g_Wo[DIM*DIM];
__device__ float g_Qa[BH*T2*HD];   // [BH][T][HD]
__device__ float g_Ka[BH*T2*HD];
__device__ float g_Vb[BH*T2*HD];
__device__ float g_Vt[BH*HD*T2];   // V transposed [BH][HD][T]
__device__ float g_Yb[BH*T2*HD];   // attention out [BH][T][HD]
__device__ float g_Y2[BT*DIM];     // attention out [BT][DIM]

// ---------------- mma helpers ----------------
__device__ __forceinline__ unsigned f2tf(float x){
    unsigned r; asm("cvt.rna.tf32.f32 %0, %1;" : "=r"(r) : "f"(x)); return r;
}
__device__ __forceinline__ void mma8(float* d, const unsigned* a, const unsigned* b){
    asm volatile("mma.sync.aligned.m16n8k8.row.col.f32.tf32.tf32.f32 "
                 "{%0,%1,%2,%3},{%4,%5,%6,%7},{%8,%9},{%0,%1,%2,%3};"
                 : "+f"(d[0]),"+f"(d[1]),"+f"(d[2]),"+f"(d[3])
                 : "r"(a[0]),"r"(a[1]),"r"(a[2]),"r"(a[3]),"r"(b[0]),"r"(b[1]));
}

// ---------------- ternary dequant ----------------
__global__ void __launch_bounds__(256) dequant_kernel(
    const float* __restrict__ w, float* __restrict__ o)
{
    int row = blockIdx.x;
    int tid = threadIdx.x;
    const float* wr = w + (size_t)row*DIM + tid*8;
    float v[8]; float s = 0.f;
    #pragma unroll
    for (int i=0;i<8;i++){ v[i]=wr[i]; s += fabsf(v[i]); }
    #pragma unroll
    for (int off=8; off; off>>=1)
        s += __shfl_xor_sync(0xffffffffu, s, off, 16);
    float scale = fmaxf(s*(1.0f/128.0f), 1e-8f);
    float inv = 1.0f/scale;
    float* orow = o + (size_t)row*DIM + tid*8;
    #pragma unroll
    for (int i=0;i<8;i++){
        float wn = v[i]*inv;
        float q = (wn > 0.5f) ? 1.0f : ((wn < -0.5f) ? -1.0f : 0.0f);
        orow[i] = q*scale;
    }
}

// ---------------- tf32 tensor-core GEMM: C[m,n] = sum_k A[m,k]*B[n,k] ---------
__global__ void __launch_bounds__(256) gemm_tf32_kernel(
    const float* __restrict__ A, const float* __restrict__ Bw,
    float* __restrict__ C, int M, int N, int K, int mode)
{
    __shared__ unsigned As[128][36];
    __shared__ unsigned Bs[128][36];
    int tid  = threadIdx.x;
    int bm   = blockIdx.y, bn = blockIdx.x;
    int warp = tid>>5, lane = tid&31;
    int wm   = (warp&1)<<6;
    int wn   = (warp>>1)<<5;
    int g    = lane>>2, t = lane&3;

    float acc[4][4][4];
    #pragma unroll
    for(int i=0;i<4;i++)
        #pragma unroll
        for(int j=0;j<4;j++)
            #pragma unroll
            for(int r=0;r<4;r++) acc[i][j][r]=0.f;

    int lr = tid>>3;
    int lk = (tid&7)<<2;
    const float* Ag = A  + (size_t)(bm*128 + lr)*K + lk;
    const float* Bg = Bw + (size_t)(bn*128 + lr)*K + lk;

    float4 av[4], bv[4];
    #pragma unroll
    for(int i=0;i<4;i++){
        av[i] = *(const float4*)(Ag + (size_t)i*32*K);
        bv[i] = *(const float4*)(Bg + (size_t)i*32*K);
    }

    for(int k0=0; k0<K; k0+=32){
        __syncthreads();
        #pragma unroll
        for(int i=0;i<4;i++){
            As[lr+i*32][lk+0]=f2tf(av[i].x); As[lr+i*32][lk+1]=f2tf(av[i].y);
            As[lr+i*32][lk+2]=f2tf(av[i].z); As[lr+i*32][lk+3]=f2tf(av[i].w);
            Bs[lr+i*32][lk+0]=f2tf(bv[i].x); Bs[lr+i*32][lk+1]=f2tf(bv[i].y);
            Bs[lr+i*32][lk+2]=f2tf(bv[i].z); Bs[lr+i*32][lk+3]=f2tf(bv[i].w);
        }
        __syncthreads();
        if (k0+32 < K){
            #pragma unroll
            for(int i=0;i<4;i++){
                av[i] = *(const float4*)(Ag + k0+32 + (size_t)i*32*K);
                bv[i] = *(const float4*)(Bg + k0+32 + (size_t)i*32*K);
            }
        }
        #pragma unroll
        for(int ks=0;ks<4;ks++){
            int c = ks*8 + t;
            unsigned af[4][4], bf[4][2];
            #pragma unroll
            for(int mi=0;mi<4;mi++){
                int row = wm + mi*16 + g;
                af[mi][0]=As[row  ][c];   af[mi][1]=As[row+8][c];
                af[mi][2]=As[row  ][c+4]; af[mi][3]=As[row+8][c+4];
            }
            #pragma unroll
            for(int ni=0;ni<4;ni++){
                int n = wn + ni*8 + g;
                bf[ni][0]=Bs[n][c]; bf[ni][1]=Bs[n][c+4];
            }
            #pragma unroll
            for(int mi=0;mi<4;mi++)
                #pragma unroll
                for(int ni=0;ni<4;ni++)
                    mma8(acc[mi][ni], af[mi], bf[ni]);
        }
    }

    #pragma unroll
    for(int mi=0;mi<4;mi++){
        #pragma unroll
        for(int ni=0;ni<4;ni++){
            int rowa = bm*128 + wm + mi*16 + g;
            int col  = bn*128 + wn + ni*8 + 2*t;
            if (mode == 0){
                float2* p0 = (float2*)(C + (size_t)rowa*N + col);
                *p0 = make_float2(acc[mi][ni][0], acc[mi][ni][1]);
                float2* p1 = (float2*)(C + (size_t)(rowa+8)*N + col);
                *p1 = make_float2(acc[mi][ni][2], acc[mi][ni][3]);
            } else {
                int h = col>>7, d = col&127;
                int m0 = rowa;
                int b0_=m0>>11, t0_=m0&2047;
                float2* p0 = (float2*)(C + ((size_t)((b0_*NH+h)*T2+t0_))*HD + d);
                *p0 = make_float2(acc[mi][ni][0], acc[mi][ni][1]);
                int m1 = rowa+8;
                int b1_=m1>>11, t1_=m1&2047;
                float2* p1 = (float2*)(C + ((size_t)((b1_*NH+h)*T2+t1_))*HD + d);
                *p1 = make_float2(acc[mi][ni][2], acc[mi][ni][3]);
            }
        }
    }
}

// ---------------- RoPE in place on [BH][T][HD] ----------------
__global__ void __launch_bounds__(256) rope_ip_kernel(float* __restrict__ a)
{
    size_t idx = (size_t)blockIdx.x*256 + threadIdx.x;   // BH*T2*64 pairs
    int j  = (int)(idx & 63);
    int t  = (int)((idx >> 6) & 2047);
    int bh = (int)(idx >> 17);
    float* p = a + ((size_t)bh*T2 + t)*HD;
    float x1 = p[j], x2 = p[j+64];
    float invf = exp2f(-(float)j * (13.287712379549449f/64.0f));
    float ang  = (float)t * invf;
    float sn, cs; sincosf(ang, &sn, &cs);
    p[j]    = x1*cs - x2*sn;
    p[j+64] = x1*sn + x2*cs;
}

// ---------------- V transpose: [BH][T][HD] -> [BH][HD][T] ----------------
__global__ void __launch_bounds__(256) transposeTH_kernel(
    const float* __restrict__ in, float* __restrict__ out)
{
    __shared__ float S[64][65];
    int t0 = blockIdx.x * 64;
    int d0 = blockIdx.y * 64;
    int bh = blockIdx.z;
    int tid = threadIdx.x;
    #pragma unroll
    for (int k=0;k<16;k++){
        int e = tid + k*256;
        int tl = e >> 6, dl = e & 63;
        S[tl][dl] = in[((size_t)bh*T2 + t0 + tl)*HD + d0 + dl];
    }
    __syncthreads();
    #pragma unroll
    for (int k=0;k<16;k++){
        int e = tid + k*256;
        int dl = e >> 6, tl = e & 63;
        out[((size_t)bh*HD + d0 + dl)*T2 + t0 + tl] = S[tl][dl];
    }
}

// ---------------- tf32 flash attention (causal) ----------------
// Q,K: [BH][T][HD]; Vt: [BH][HD][T]; Ob: [BH][T][HD]
// BM=128, BN=64. 256 threads = 8 warps; warp w owns rows [w*16, w*16+16).
#define QS_STR 132
#define VS_STR 68
#define PS_STR 68
#define FL2_U32 (128*QS_STR + 64*QS_STR + 128*VS_STR + 128*PS_STR)
#define FL2_SMEM (FL2_U32*4)

__global__ void __launch_bounds__(256) flash2_kernel(
    const float* __restrict__ Q, const float* __restrict__ K,
    const float* __restrict__ Vt, float* __restrict__ Ob)
{
    extern __shared__ unsigned sm2[];
    unsigned* Qs = sm2;                    // [128][132]
    unsigned* Ks = Qs + 128*QS_STR;        // [64][132]
    unsigned* Vs = Ks + 64*QS_STR;         // [128][68]  (Vs[d][key])
    unsigned* Ps = Vs + 128*VS_STR;        // [128][68]  (Ps[m][key], tf32 bits)

    int qb  = (int)(gridDim.x - 1 - blockIdx.x);   // heavy blocks first
    int bh  = blockIdx.y;
    int tid = threadIdx.x;
    int warp = tid >> 5, lane = tid & 31;
    int g = lane >> 2, t = lane & 3;

    const float SC = 0.08838834764831845f;  // 1/sqrt(128)

    // stage Q (scaled) once
    const float* qg = Q + ((size_t)bh*T2 + qb*128)*HD;
    #pragma unroll
    for (int it=0; it<16; it++){
        int idx = tid + it*256;
        int r = idx >> 5, c = (idx & 31) << 2;
        float4 v = *(const float4*)(qg + (size_t)r*HD + c);
        uint4 u = make_uint4(f2tf(v.x*SC), f2tf(v.y*SC), f2tf(v.z*SC), f2tf(v.w*SC));
        *(uint4*)&Qs[r*QS_STR + c] = u;
    }

    float m0 = -1e30f, m1 = -1e30f, l0 = 0.f, l1 = 0.f;
    float o[16][4];
    #pragma unroll
    for (int i=0;i<16;i++)
        #pragma unroll
        for (int r=0;r<4;r++) o[i][r]=0.f;

    const float* kg = K  + (size_t)bh*T2*HD;
    const float* vg = Vt + (size_t)bh*HD*T2;
    int prow = warp*16 + g;
    int nkb = 2*qb + 2;

    for (int kb=0; kb<nkb; kb++){
        __syncthreads();
        // stage K tile [64][128]
        #pragma unroll
        for (int it=0; it<8; it++){
            int idx = tid + it*256;
            int r = idx >> 5, c = (idx & 31) << 2;
            float4 v = *(const float4*)(kg + (size_t)(kb*64 + r)*HD + c);
            uint4 u = make_uint4(f2tf(v.x), f2tf(v.y), f2tf(v.z), f2tf(v.w));
            *(uint4*)&Ks[r*QS_STR + c] = u;
        }
        // stage V tile transposed [128 d][64 key]
        #pragma unroll
        for (int it=0; it<8; it++){
            int idx = tid + it*256;
            int d = idx >> 4, c = (idx & 15) << 2;
            float4 v = *(const float4*)(vg + (size_t)d*T2 + kb*64 + c);
            uint4 u = make_uint4(f2tf(v.x), f2tf(v.y), f2tf(v.z), f2tf(v.w));
            *(uint4*)&Vs[d*VS_STR + c] = u;
        }
        __syncthreads();

        // S = Q K^T : per warp 16 x 64
        float s[8][4];
        #pragma unroll
        for (int ni=0;ni<8;ni++)
            #pragma unroll
            for (int r=0;r<4;r++) s[ni][r]=0.f;
        #pragma unroll
        for (int ks=0; ks<16; ks++){
            int c = ks*8 + t;
            unsigned af[4];
            af[0]=Qs[prow*QS_STR + c];       af[1]=Qs[(prow+8)*QS_STR + c];
            af[2]=Qs[prow*QS_STR + c + 4];   af[3]=Qs[(prow+8)*QS_STR + c + 4];
            #pragma unroll
            for (int ni=0;ni<8;ni++){
                unsigned bf[2];
                int n = ni*8 + g;
                bf[0]=Ks[n*QS_STR + c]; bf[1]=Ks[n*QS_STR + c + 4];
                mma8(s[ni], af, bf);
            }
        }

        // causal mask (only near diagonal)
        if (kb >= 2*qb){
            int q0 = qb*128 + prow, q1 = q0 + 8;
            #pragma unroll
            for (int ni=0;ni<8;ni++){
                int k0 = kb*64 + ni*8 + 2*t;
                if (k0   > q0) s[ni][0] = -1e30f;
                if (k0+1 > q0) s[ni][1] = -1e30f;
                if (k0   > q1) s[ni][2] = -1e30f;
                if (k0+1 > q1) s[ni][3] = -1e30f;
            }
        }

        // online softmax (rows g and g+8)
        float mx0 = -1e30f, mx1 = -1e30f;
        #pragma unroll
        for (int ni=0;ni<8;ni++){
            mx0 = fmaxf(mx0, fmaxf(s[ni][0], s[ni][1]));
            mx1 = fmaxf(mx1, fmaxf(s[ni][2], s[ni][3]));
        }
        #pragma unroll
        for (int off=1; off<4; off<<=1){
            mx0 = fmaxf(mx0, __shfl_xor_sync(0xffffffffu, mx0, off, 4));
            mx1 = fmaxf(mx1, __shfl_xor_sync(0xffffffffu, mx1, off, 4));
        }
        float nm0 = fmaxf(m0, mx0), nm1 = fmaxf(m1, mx1);
        float a0 = __expf(m0 - nm0), a1 = __expf(m1 - nm1);
        m0 = nm0; m1 = nm1;
        float sum0 = 0.f, sum1 = 0.f;
        #pragma unroll
        for (int ni=0;ni<8;ni++){
            s[ni][0] = __expf(s[ni][0]-nm0); sum0 += s[ni][0];
            s[ni][1] = __expf(s[ni][1]-nm0); sum0 += s[ni][1];
            s[ni][2] = __expf(s[ni][2]-nm1); sum1 += s[ni][2];
            s[ni][3] = __expf(s[ni][3]-nm1); sum1 += s[ni][3];
        }
        #pragma unroll
        for (int off=1; off<4; off<<=1){
            sum0 += __shfl_xor_sync(0xffffffffu, sum0, off, 4);
            sum1 += __shfl_xor_sync(0xffffffffu, sum1, off, 4);
        }
        l0 = l0*a0 + sum0;
        l1 = l1*a1 + sum1;
        #pragma unroll
        for (int ti=0;ti<16;ti++){
            o[ti][0]*=a0; o[ti][1]*=a0; o[ti][2]*=a1; o[ti][3]*=a1;
        }

        // store P (tf32) to smem
        #pragma unroll
        for (int ni=0;ni<8;ni++){
            int cc = ni*8 + 2*t;
            Ps[prow*PS_STR + cc]     = f2tf(s[ni][0]);
            Ps[prow*PS_STR + cc + 1] = f2tf(s[ni][1]);
            Ps[(prow+8)*PS_STR + cc]     = f2tf(s[ni][2]);
            Ps[(prow+8)*PS_STR + cc + 1] = f2tf(s[ni][3]);
        }
        __syncwarp();

        // O += P V : per warp 16 x 128, k=64
        #pragma unroll
        for (int ks=0; ks<8; ks++){
            int c = ks*8 + t;
            unsigned af[4];
            af[0]=Ps[prow*PS_STR + c];     af[1]=Ps[(prow+8)*PS_STR + c];
            af[2]=Ps[prow*PS_STR + c + 4]; af[3]=Ps[(prow+8)*PS_STR + c + 4];
            #pragma unroll
            for (int ti=0;ti<16;ti++){
                unsigned bf[2];
                int n = ti*8 + g;
                bf[0]=Vs[n*VS_STR + c]; bf[1]=Vs[n*VS_STR + c + 4];
                mma8(o[ti], af, bf);
            }
        }
        __syncwarp();
    }

    float i0 = 1.0f/l0, i1 = 1.0f/l1;
    int rowg = qb*128 + prow;
    float* ob = Ob + (size_t)bh*T2*HD;
    #pragma unroll
    for (int ti=0;ti<16;ti++){
        int col = ti*8 + 2*t;
        *(float2*)(ob + (size_t)rowg*HD + col)     = make_float2(o[ti][0]*i0, o[ti][1]*i0);
        *(float2*)(ob + (size_t)(rowg+8)*HD + col) = make_float2(o[ti][2]*i1, o[ti][3]*i1);
    }
}

// ---------------- [BH][T][HD] -> [BT][DIM] ----------------
__global__ void __launch_bounds__(256) transpose_kernel(
    const float* __restrict__ Yb, float* __restrict__ Y2)
{
    size_t i = (size_t)blockIdx.x*256 + threadIdx.x;
    int d = (int)(i & 127);
    size_t r = i >> 7;
    int t = (int)(r & 2047);
    size_t r2 = r >> 11;
    int h = (int)(r2 & 15);
    int b = (int)(r2 >> 4);
    Y2[((size_t)(b*T2 + t))*DIM + h*HD + d] = Yb[i];
}

// ---------------- launch ----------------
extern "C" void kernel_launch(void* const* d_in, const int* in_sizes, int n_in,
                              void* d_out, int out_size)
{
    const float* x  = (const float*)d_in[0];
    const float* wq = (const float*)d_in[1];
    const float* wk = (const float*)d_in[2];
    const float* wv = (const float*)d_in[3];
    const float* wo = (const float*)d_in[4];
    float* out = (float*)d_out;

    float *Wq,*Wk,*Wv,*Wo,*Qa,*Ka,*Vb,*Vt,*Yb,*Y2;
    cudaGetSymbolAddress((void**)&Wq, g_Wq);
    cudaGetSymbolAddress((void**)&Wk, g_Wk);
    cudaGetSymbolAddress((void**)&Wv, g_Wv);
    cudaGetSymbolAddress((void**)&Wo, g_Wo);
    cudaGetSymbolAddress((void**)&Qa, g_Qa);
    cudaGetSymbolAddress((void**)&Ka, g_Ka);
    cudaGetSymbolAddress((void**)&Vb, g_Vb);
    cudaGetSymbolAddress((void**)&Vt, g_Vt);
    cudaGetSymbolAddress((void**)&Yb, g_Yb);
    cudaGetSymbolAddress((void**)&Y2, g_Y2);

    cudaFuncSetAttribute(flash2_kernel,
        cudaFuncAttributeMaxDynamicSharedMemorySize, FL2_SMEM);

    dequant_kernel<<<DIM,256>>>(wq, Wq);
    dequant_kernel<<<DIM,256>>>(wk, Wk);
    dequant_kernel<<<DIM,256>>>(wv, Wv);
    dequant_kernel<<<DIM,256>>>(wo, Wo);

    dim3 gg(DIM/128, BT/128);
    gemm_tf32_kernel<<<gg,256>>>(x, Wq, Qa, BT, DIM, DIM, 1);
    gemm_tf32_kernel<<<gg,256>>>(x, Wk, Ka, BT, DIM, DIM, 1);
    gemm_tf32_kernel<<<gg,256>>>(x, Wv, Vb, BT, DIM, DIM, 1);

    rope_ip_kernel<<<(BH*T2*64)/256, 256>>>(Qa);
    rope_ip_kernel<<<(BH*T2*64)/256, 256>>>(Ka);

    transposeTH_kernel<<<dim3(T2/64, HD/64, BH), 256>>>(Vb, Vt);

    flash2_kernel<<<dim3(T2/128, BH), 256, FL2_SMEM>>>(Qa, Ka, Vt, Yb);

    transpose_kernel<<<(BT*DIM)/256, 256>>>(Yb, Y2);

    gemm_tf32_kernel<<<gg,256>>>(Y2, Wo, out, BT, DIM, DIM, 0);
}

// round 4
// speedup vs baseline: 4.0112x; 1.0996x over previous
#include <cuda_runtime.h>
#include <math.h>

#define DIM 2048
#define NH  16
#define HD  128
#define B2  2
#define T2  2048
#define BT  4096   // B*T
#define BH  32     // B*NH

// ---------------- device scratch ----------------
__device__ float g_Wq[DIM*DIM];
__device__ float g_Wk[DIM*DIM];
__device__ float g_Wv[DIM*DIM];
__device__ float g_Wo[DIM*DIM];
__device__ float g_Xr[BT*DIM];     // tf32-rounded x
__device__ float g_Qa[BH*T2*HD];   // [BH][T][HD]
__device__ float g_Ka[BH*T2*HD];
__device__ float g_Vb[BH*T2*HD];
__device__ float g_Vt[BH*HD*T2];   // V transposed [BH][HD][T], tf32-rounded
__device__ float g_Y2[BT*DIM];     // attention out [BT][DIM], tf32-rounded

// ---------------- helpers ----------------
__device__ __forceinline__ unsigned f2tf(float x){
    unsigned r; asm("cvt.rna.tf32.f32 %0, %1;" : "=r"(r) : "f"(x)); return r;
}
__device__ __forceinline__ float rtf(float x){ return __uint_as_float(f2tf(x)); }

__device__ __forceinline__ void mma8(float* d, const unsigned* a, const unsigned* b){
    asm volatile("mma.sync.aligned.m16n8k8.row.col.f32.tf32.tf32.f32 "
                 "{%0,%1,%2,%3},{%4,%5,%6,%7},{%8,%9},{%0,%1,%2,%3};"
                 : "+f"(d[0]),"+f"(d[1]),"+f"(d[2]),"+f"(d[3])
                 : "r"(a[0]),"r"(a[1]),"r"(a[2]),"r"(a[3]),"r"(b[0]),"r"(b[1]));
}
__device__ __forceinline__ void ldsm4(unsigned* r, unsigned addr){
    asm volatile("ldmatrix.sync.aligned.m8n8.x4.shared.b16 {%0,%1,%2,%3}, [%4];"
                 : "=r"(r[0]),"=r"(r[1]),"=r"(r[2]),"=r"(r[3]) : "r"(addr));
}

// ---------------- ternary dequant (emits tf32-rounded) ----------------
__global__ void __launch_bounds__(256) dequant_kernel(
    const float* __restrict__ w, float* __restrict__ o)
{
    int row = blockIdx.x;
    int tid = threadIdx.x;
    const float* wr = w + (size_t)row*DIM + tid*8;
    float v[8]; float s = 0.f;
    #pragma unroll
    for (int i=0;i<8;i++){ v[i]=wr[i]; s += fabsf(v[i]); }
    #pragma unroll
    for (int off=8; off; off>>=1)
        s += __shfl_xor_sync(0xffffffffu, s, off, 16);
    float scale = fmaxf(s*(1.0f/128.0f), 1e-8f);
    float inv = 1.0f/scale;
    float* orow = o + (size_t)row*DIM + tid*8;
    #pragma unroll
    for (int i=0;i<8;i++){
        float wn = v[i]*inv;
        float q = (wn > 0.5f) ? 1.0f : ((wn < -0.5f) ? -1.0f : 0.0f);
        orow[i] = rtf(q*scale);
    }
}

// ---------------- tf32 rounding pass ----------------
__global__ void __launch_bounds__(256) round_kernel(
    const float* __restrict__ in, float* __restrict__ out)
{
    size_t i = ((size_t)blockIdx.x*256 + threadIdx.x)*4;
    float4 v = *(const float4*)(in + i);
    v.x=rtf(v.x); v.y=rtf(v.y); v.z=rtf(v.z); v.w=rtf(v.w);
    *(float4*)(out + i) = v;
}

// ---------------- tf32 tensor-core GEMM: C[m,n] = sum_k A[m,k]*B[n,k] ---------
// A,B already tf32-rounded. 128x128 tile, BK=32, 8 warps (2m x 4n), warp 64x32.
// Fragments via ldmatrix(b16 trick). mode 0: row-major; mode 1: [B][H][T][HD].
__global__ void __launch_bounds__(256) gemm_tf32_kernel(
    const float* __restrict__ A, const float* __restrict__ Bw,
    float* __restrict__ C, int M, int N, int K, int mode)
{
    __shared__ __align__(16) unsigned As[128][36];
    __shared__ __align__(16) unsigned Bs[128][36];
    int tid  = threadIdx.x;
    int bm   = blockIdx.y, bn = blockIdx.x;
    int warp = tid>>5, lane = tid&31;
    int wm   = (warp&1)<<6;
    int wn   = (warp>>1)<<5;
    int g    = lane>>2, t = lane&3;

    // ldmatrix lane address offsets
    int arow = ((lane>>3)&1)*8 + (lane&7);
    int acol = (lane>>4)*4;
    int bmat = lane>>3;
    int brow = (bmat>>1)*8 + (lane&7);
    int bcol = (bmat&1)*4;
    unsigned Abase = (unsigned)__cvta_generic_to_shared(&As[0][0]);
    unsigned Bbase = (unsigned)__cvta_generic_to_shared(&Bs[0][0]);
    unsigned a_lane = Abase + ((wm + arow)*36 + acol)*4;
    unsigned b_lane = Bbase + ((wn + brow)*36 + bcol)*4;

    float acc[4][4][4];
    #pragma unroll
    for(int i=0;i<4;i++)
        #pragma unroll
        for(int j=0;j<4;j++)
            #pragma unroll
            for(int r=0;r<4;r++) acc[i][j][r]=0.f;

    int lr = tid>>3;
    int lk = (tid&7)<<2;
    const float* Ag = A  + (size_t)(bm*128 + lr)*K + lk;
    const float* Bg = Bw + (size_t)(bn*128 + lr)*K + lk;

    uint4 av[4], bv[4];
    #pragma unroll
    for(int i=0;i<4;i++){
        av[i] = *(const uint4*)(Ag + (size_t)i*32*K);
        bv[i] = *(const uint4*)(Bg + (size_t)i*32*K);
    }

    for(int k0=0; k0<K; k0+=32){
        __syncthreads();
        #pragma unroll
        for(int i=0;i<4;i++){
            *(uint4*)&As[lr+i*32][lk] = av[i];
            *(uint4*)&Bs[lr+i*32][lk] = bv[i];
        }
        __syncthreads();
        if (k0+32 < K){
            #pragma unroll
            for(int i=0;i<4;i++){
                av[i] = *(const uint4*)(Ag + k0+32 + (size_t)i*32*K);
                bv[i] = *(const uint4*)(Bg + k0+32 + (size_t)i*32*K);
            }
        }
        #pragma unroll
        for(int ks=0;ks<4;ks++){
            unsigned af[4][4], bf[2][4];
            #pragma unroll
            for(int mi=0;mi<4;mi++)
                ldsm4(af[mi], a_lane + (mi*16*36 + ks*8)*4);
            #pragma unroll
            for(int p=0;p<2;p++)
                ldsm4(bf[p], b_lane + (p*16*36 + ks*8)*4);
            #pragma unroll
            for(int mi=0;mi<4;mi++)
                #pragma unroll
                for(int ni=0;ni<4;ni++)
                    mma8(acc[mi][ni], af[mi], &bf[ni>>1][(ni&1)*2]);
        }
    }

    #pragma unroll
    for(int mi=0;mi<4;mi++){
        #pragma unroll
        for(int ni=0;ni<4;ni++){
            int rowa = bm*128 + wm + mi*16 + g;
            int col  = bn*128 + wn + ni*8 + 2*t;
            if (mode == 0){
                float2* p0 = (float2*)(C + (size_t)rowa*N + col);
                *p0 = make_float2(acc[mi][ni][0], acc[mi][ni][1]);
                float2* p1 = (float2*)(C + (size_t)(rowa+8)*N + col);
                *p1 = make_float2(acc[mi][ni][2], acc[mi][ni][3]);
            } else {
                int h = col>>7, d = col&127;
                int m0 = rowa;
                int b0_=m0>>11, t0_=m0&2047;
                float2* p0 = (float2*)(C + ((size_t)((b0_*NH+h)*T2+t0_))*HD + d);
                *p0 = make_float2(acc[mi][ni][0], acc[mi][ni][1]);
                int m1 = rowa+8;
                int b1_=m1>>11, t1_=m1&2047;
                float2* p1 = (float2*)(C + ((size_t)((b1_*NH+h)*T2+t1_))*HD + d);
                *p1 = make_float2(acc[mi][ni][2], acc[mi][ni][3]);
            }
        }
    }
}

// ---------------- RoPE in place, emits tf32-rounded (scale folded) -----------
__global__ void __launch_bounds__(256) rope_ip_kernel(float* __restrict__ a, float scale)
{
    size_t idx = (size_t)blockIdx.x*256 + threadIdx.x;   // BH*T2*64 pairs
    int j  = (int)(idx & 63);
    int t  = (int)((idx >> 6) & 2047);
    int bh = (int)(idx >> 17);
    float* p = a + ((size_t)bh*T2 + t)*HD;
    float x1 = p[j], x2 = p[j+64];
    float invf = exp2f(-(float)j * (13.287712379549449f/64.0f));
    float ang  = (float)t * invf;
    float sn, cs; sincosf(ang, &sn, &cs);
    p[j]    = rtf((x1*cs - x2*sn)*scale);
    p[j+64] = rtf((x1*sn + x2*cs)*scale);
}

// ---------------- V transpose: [BH][T][HD] -> [BH][HD][T], rounded ----------
__global__ void __launch_bounds__(256) transposeTH_kernel(
    const float* __restrict__ in, float* __restrict__ out)
{
    __shared__ float S[64][65];
    int t0 = blockIdx.x * 64;
    int d0 = blockIdx.y * 64;
    int bh = blockIdx.z;
    int tid = threadIdx.x;
    #pragma unroll
    for (int k=0;k<16;k++){
        int e = tid + k*256;
        int tl = e >> 6, dl = e & 63;
        S[tl][dl] = in[((size_t)bh*T2 + t0 + tl)*HD + d0 + dl];
    }
    __syncthreads();
    #pragma unroll
    for (int k=0;k<16;k++){
        int e = tid + k*256;
        int dl = e >> 6, tl = e & 63;
        out[((size_t)bh*HD + d0 + dl)*T2 + t0 + tl] = rtf(S[tl][dl]);
    }
}

// ---------------- tf32 flash attention (causal) ----------------
// Q (pre-scaled, rounded), K (rounded): [BH][T][HD]; Vt (rounded): [BH][HD][T]
// Output written directly to Y2 [BT][DIM], tf32-rounded.
#define QS_STR 132
#define VS_STR 68
#define PS_STR 68
#define FL2_U32 (128*QS_STR + 64*QS_STR + 128*VS_STR + 128*PS_STR)
#define FL2_SMEM (FL2_U32*4)

__global__ void __launch_bounds__(256) flash2_kernel(
    const float* __restrict__ Q, const float* __restrict__ K,
    const float* __restrict__ Vt, float* __restrict__ Y2)
{
    extern __shared__ __align__(16) unsigned sm2[];
    unsigned* Qs = sm2;                    // [128][132]
    unsigned* Ks = Qs + 128*QS_STR;        // [64][132]
    unsigned* Vs = Ks + 64*QS_STR;         // [128][68]  Vs[d][key]
    unsigned* Ps = Vs + 128*VS_STR;        // [128][68]  Ps[m][key]

    int qb  = (int)(gridDim.x - 1 - blockIdx.x);
    int bh  = blockIdx.y;
    int tid = threadIdx.x;
    int warp = tid >> 5, lane = tid & 31;
    int g = lane >> 2, t = lane & 3;

    // ldmatrix lane offsets
    int arow = ((lane>>3)&1)*8 + (lane&7);
    int acol = (lane>>4)*4;
    int bmat = lane>>3;
    int brow = (bmat>>1)*8 + (lane&7);
    int bcol = (bmat&1)*4;
    unsigned Qbase = (unsigned)__cvta_generic_to_shared(Qs);
    unsigned Kbase = (unsigned)__cvta_generic_to_shared(Ks);
    unsigned Vbase = (unsigned)__cvta_generic_to_shared(Vs);
    unsigned Pbase = (unsigned)__cvta_generic_to_shared(Ps);
    unsigned q_lane = Qbase + ((warp*16 + arow)*QS_STR + acol)*4;
    unsigned k_lane = Kbase + (brow*QS_STR + bcol)*4;
    unsigned p_lane = Pbase + ((warp*16 + arow)*PS_STR + acol)*4;
    unsigned v_lane = Vbase + (brow*VS_STR + bcol)*4;

    // stage Q once (already scaled + rounded)
    const float* qg = Q + ((size_t)bh*T2 + qb*128)*HD;
    #pragma unroll
    for (int it=0; it<16; it++){
        int idx = tid + it*256;
        int r = idx >> 5, c = (idx & 31) << 2;
        *(uint4*)&Qs[r*QS_STR + c] = *(const uint4*)(qg + (size_t)r*HD + c);
    }

    float m0 = -1e30f, m1 = -1e30f, l0 = 0.f, l1 = 0.f;
    float o[16][4];
    #pragma unroll
    for (int i=0;i<16;i++)
        #pragma unroll
        for (int r=0;r<4;r++) o[i][r]=0.f;

    const float* kg = K  + (size_t)bh*T2*HD;
    const float* vg = Vt + (size_t)bh*HD*T2;
    int prow = warp*16 + g;
    int nkb = 2*qb + 2;

    for (int kb=0; kb<nkb; kb++){
        __syncthreads();
        #pragma unroll
        for (int it=0; it<8; it++){
            int idx = tid + it*256;
            int r = idx >> 5, c = (idx & 31) << 2;
            *(uint4*)&Ks[r*QS_STR + c] = *(const uint4*)(kg + (size_t)(kb*64 + r)*HD + c);
        }
        #pragma unroll
        for (int it=0; it<8; it++){
            int idx = tid + it*256;
            int d = idx >> 4, c = (idx & 15) << 2;
            *(uint4*)&Vs[d*VS_STR + c] = *(const uint4*)(vg + (size_t)d*T2 + kb*64 + c);
        }
        __syncthreads();

        // S = Q K^T : per warp 16 x 64
        float s[8][4];
        #pragma unroll
        for (int ni=0;ni<8;ni++)
            #pragma unroll
            for (int r=0;r<4;r++) s[ni][r]=0.f;
        #pragma unroll
        for (int ks=0; ks<16; ks++){
            unsigned af[4], kf[4][4];
            ldsm4(af, q_lane + ks*32);
            #pragma unroll
            for (int p=0;p<4;p++)
                ldsm4(kf[p], k_lane + (p*16*QS_STR + ks*8)*4);
            #pragma unroll
            for (int ni=0;ni<8;ni++)
                mma8(s[ni], af, &kf[ni>>1][(ni&1)*2]);
        }

        // causal mask
        if (kb >= 2*qb){
            int q0 = qb*128 + prow, q1 = q0 + 8;
            #pragma unroll
            for (int ni=0;ni<8;ni++){
                int k0 = kb*64 + ni*8 + 2*t;
                if (k0   > q0) s[ni][0] = -1e30f;
                if (k0+1 > q0) s[ni][1] = -1e30f;
                if (k0   > q1) s[ni][2] = -1e30f;
                if (k0+1 > q1) s[ni][3] = -1e30f;
            }
        }

        // online softmax
        float mx0 = -1e30f, mx1 = -1e30f;
        #pragma unroll
        for (int ni=0;ni<8;ni++){
            mx0 = fmaxf(mx0, fmaxf(s[ni][0], s[ni][1]));
            mx1 = fmaxf(mx1, fmaxf(s[ni][2], s[ni][3]));
        }
        #pragma unroll
        for (int off=1; off<4; off<<=1){
            mx0 = fmaxf(mx0, __shfl_xor_sync(0xffffffffu, mx0, off, 4));
            mx1 = fmaxf(mx1, __shfl_xor_sync(0xffffffffu, mx1, off, 4));
        }
        float nm0 = fmaxf(m0, mx0), nm1 = fmaxf(m1, mx1);
        float a0 = __expf(m0 - nm0), a1 = __expf(m1 - nm1);
        m0 = nm0; m1 = nm1;
        float sum0 = 0.f, sum1 = 0.f;
        #pragma unroll
        for (int ni=0;ni<8;ni++){
            s[ni][0] = __expf(s[ni][0]-nm0); sum0 += s[ni][0];
            s[ni][1] = __expf(s[ni][1]-nm0); sum0 += s[ni][1];
            s[ni][2] = __expf(s[ni][2]-nm1); sum1 += s[ni][2];
            s[ni][3] = __expf(s[ni][3]-nm1); sum1 += s[ni][3];
        }
        #pragma unroll
        for (int off=1; off<4; off<<=1){
            sum0 += __shfl_xor_sync(0xffffffffu, sum0, off, 4);
            sum1 += __shfl_xor_sync(0xffffffffu, sum1, off, 4);
        }
        l0 = l0*a0 + sum0;
        l1 = l1*a1 + sum1;
        #pragma unroll
        for (int ti=0;ti<16;ti++){
            o[ti][0]*=a0; o[ti][1]*=a0; o[ti][2]*=a1; o[ti][3]*=a1;
        }

        // P -> smem (tf32)
        #pragma unroll
        for (int ni=0;ni<8;ni++){
            int cc = ni*8 + 2*t;
            Ps[prow*PS_STR + cc]     = f2tf(s[ni][0]);
            Ps[prow*PS_STR + cc + 1] = f2tf(s[ni][1]);
            Ps[(prow+8)*PS_STR + cc]     = f2tf(s[ni][2]);
            Ps[(prow+8)*PS_STR + cc + 1] = f2tf(s[ni][3]);
        }
        __syncwarp();

        // O += P V
        #pragma unroll
        for (int ks=0; ks<8; ks++){
            unsigned af[4], vf[8][4];
            ldsm4(af, p_lane + ks*32);
            #pragma unroll
            for (int p=0;p<8;p++)
                ldsm4(vf[p], v_lane + (p*16*VS_STR + ks*8)*4);
            #pragma unroll
            for (int ti=0;ti<16;ti++)
                mma8(o[ti], af, &vf[ti>>1][(ti&1)*2]);
        }
        __syncwarp();
    }

    // write directly to [BT][DIM], tf32-rounded
    float i0 = 1.0f/l0, i1 = 1.0f/l1;
    int trow = qb*128 + prow;
    int b_ = bh >> 4, h = bh & 15;
    float* yr = Y2 + ((size_t)b_*T2)*DIM + h*HD;
    #pragma unroll
    for (int ti=0;ti<16;ti++){
        int col = ti*8 + 2*t;
        *(float2*)(yr + (size_t)trow*DIM + col) =
            make_float2(rtf(o[ti][0]*i0), rtf(o[ti][1]*i0));
        *(float2*)(yr + (size_t)(trow+8)*DIM + col) =
            make_float2(rtf(o[ti][2]*i1), rtf(o[ti][3]*i1));
    }
}

// ---------------- launch ----------------
extern "C" void kernel_launch(void* const* d_in, const int* in_sizes, int n_in,
                              void* d_out, int out_size)
{
    const float* x  = (const float*)d_in[0];
    const float* wq = (const float*)d_in[1];
    const float* wk = (const float*)d_in[2];
    const float* wv = (const float*)d_in[3];
    const float* wo = (const float*)d_in[4];
    float* out = (float*)d_out;

    float *Wq,*Wk,*Wv,*Wo,*Xr,*Qa,*Ka,*Vb,*Vt,*Y2;
    cudaGetSymbolAddress((void**)&Wq, g_Wq);
    cudaGetSymbolAddress((void**)&Wk, g_Wk);
    cudaGetSymbolAddress((void**)&Wv, g_Wv);
    cudaGetSymbolAddress((void**)&Wo, g_Wo);
    cudaGetSymbolAddress((void**)&Xr, g_Xr);
    cudaGetSymbolAddress((void**)&Qa, g_Qa);
    cudaGetSymbolAddress((void**)&Ka, g_Ka);
    cudaGetSymbolAddress((void**)&Vb, g_Vb);
    cudaGetSymbolAddress((void**)&Vt, g_Vt);
    cudaGetSymbolAddress((void**)&Y2, g_Y2);

    cudaFuncSetAttribute(flash2_kernel,
        cudaFuncAttributeMaxDynamicSharedMemorySize, FL2_SMEM);

    dequant_kernel<<<DIM,256>>>(wq, Wq);
    dequant_kernel<<<DIM,256>>>(wk, Wk);
    dequant_kernel<<<DIM,256>>>(wv, Wv);
    dequant_kernel<<<DIM,256>>>(wo, Wo);
    round_kernel<<<(BT*DIM)/1024, 256>>>(x, Xr);

    dim3 gg(DIM/128, BT/128);
    gemm_tf32_kernel<<<gg,256>>>(Xr, Wq, Qa, BT, DIM, DIM, 1);
    gemm_tf32_kernel<<<gg,256>>>(Xr, Wk, Ka, BT, DIM, DIM, 1);
    gemm_tf32_kernel<<<gg,256>>>(Xr, Wv, Vb, BT, DIM, DIM, 1);

    rope_ip_kernel<<<(BH*T2*64)/256, 256>>>(Qa, 0.08838834764831845f);
    rope_ip_kernel<<<(BH*T2*64)/256, 256>>>(Ka, 1.0f);

    transposeTH_kernel<<<dim3(T2/64, HD/64, BH), 256>>>(Vb, Vt);

    flash2_kernel<<<dim3(T2/128, BH), 256, FL2_SMEM>>>(Qa, Ka, Vt, Y2);

    gemm_tf32_kernel<<<gg,256>>>(Y2, Wo, out, BT, DIM, DIM, 0);
}

// round 5
// speedup vs baseline: 7.2733x; 1.8132x over previous
#include <cuda_runtime.h>
#include <cuda_fp16.h>
#include <math.h>

#define DIM 2048
#define NH  16
#define HD  128
#define B2  2
#define T2  2048
#define BT  4096   // B*T
#define BH  32     // B*NH

// ---------------- device scratch ----------------
__device__ __half g_Wq[DIM*DIM];
__device__ __half g_Wk[DIM*DIM];
__device__ __half g_Wv[DIM*DIM];
__device__ __half g_Wo[DIM*DIM];
__device__ __half g_Xh[BT*DIM];      // x in fp16
__device__ float  g_Qa[BH*T2*HD];    // projections fp32 [BH][T][HD]
__device__ float  g_Ka[BH*T2*HD];
__device__ float  g_Vb[BH*T2*HD];
__device__ __half g_Qh[BH*T2*HD];    // post-RoPE fp16 (scale folded)
__device__ __half g_Kh[BH*T2*HD];
__device__ __half g_Vt[BH*HD*T2];    // V transposed fp16 [BH][HD][T]
__device__ __half g_Y2[BT*DIM];      // attention out fp16 [BT][DIM]

// ---------------- helpers ----------------
__device__ __forceinline__ void mma16(float* d, const unsigned* a, const unsigned* b){
    asm volatile("mma.sync.aligned.m16n8k16.row.col.f32.f16.f16.f32 "
                 "{%0,%1,%2,%3},{%4,%5,%6,%7},{%8,%9},{%0,%1,%2,%3};"
                 : "+f"(d[0]),"+f"(d[1]),"+f"(d[2]),"+f"(d[3])
                 : "r"(a[0]),"r"(a[1]),"r"(a[2]),"r"(a[3]),"r"(b[0]),"r"(b[1]));
}
__device__ __forceinline__ void ldsm4(unsigned* r, unsigned addr){
    asm volatile("ldmatrix.sync.aligned.m8n8.x4.shared.b16 {%0,%1,%2,%3}, [%4];"
                 : "=r"(r[0]),"=r"(r[1]),"=r"(r[2]),"=r"(r[3]) : "r"(addr));
}

// ---------------- ternary dequant -> fp16 ----------------
__global__ void __launch_bounds__(256) dequant_kernel(
    const float* __restrict__ w, __half* __restrict__ o)
{
    int row = blockIdx.x;
    int tid = threadIdx.x;
    const float* wr = w + (size_t)row*DIM + tid*8;
    float v[8]; float s = 0.f;
    #pragma unroll
    for (int i=0;i<8;i++){ v[i]=wr[i]; s += fabsf(v[i]); }
    #pragma unroll
    for (int off=8; off; off>>=1)
        s += __shfl_xor_sync(0xffffffffu, s, off, 16);
    float scale = fmaxf(s*(1.0f/128.0f), 1e-8f);
    float inv = 1.0f/scale;
    __half* orow = o + (size_t)row*DIM + tid*8;
    #pragma unroll
    for (int i=0;i<4;i++){
        float wn0 = v[2*i]*inv, wn1 = v[2*i+1]*inv;
        float q0 = (wn0 > 0.5f) ? 1.0f : ((wn0 < -0.5f) ? -1.0f : 0.0f);
        float q1 = (wn1 > 0.5f) ? 1.0f : ((wn1 < -0.5f) ? -1.0f : 0.0f);
        *(__half2*)(orow + 2*i) = __floats2half2_rn(q0*scale, q1*scale);
    }
}

// ---------------- f32 -> f16 convert ----------------
__global__ void __launch_bounds__(256) tohalf_kernel(
    const float* __restrict__ in, __half* __restrict__ out)
{
    size_t i = ((size_t)blockIdx.x*256 + threadIdx.x)*8;
    float4 a = *(const float4*)(in + i);
    float4 b = *(const float4*)(in + i + 4);
    __half2 h[4];
    h[0]=__floats2half2_rn(a.x,a.y); h[1]=__floats2half2_rn(a.z,a.w);
    h[2]=__floats2half2_rn(b.x,b.y); h[3]=__floats2half2_rn(b.z,b.w);
    *(uint4*)(out + i) = *(uint4*)h;
}

// ---------------- fp16 tensor-core GEMM: C[m,n] = sum_k A[m,k]*B[n,k] --------
// A,B fp16. 128x128 tile, BK=64 halves, 8 warps (2m x 4n), warp 64x32.
// mode 0: C fp32 row-major [M][N].  mode 1: C fp32 scatter to [B][H][T][HD].
#define AH 72
__global__ void __launch_bounds__(256) gemm_f16_kernel(
    const __half* __restrict__ A, const __half* __restrict__ Bw,
    float* __restrict__ C, int M, int N, int K, int mode)
{
    __shared__ __align__(16) __half As[128*AH];
    __shared__ __align__(16) __half Bs[128*AH];
    int tid  = threadIdx.x;
    int bm   = blockIdx.y, bn = blockIdx.x;
    int warp = tid>>5, lane = tid&31;
    int wm   = (warp&1)<<6;
    int wn   = (warp>>1)<<5;
    int g    = lane>>2, t = lane&3;

    int arow = ((lane>>3)&1)*8 + (lane&7);
    int acol = (lane>>4)*8;
    int brow = ((lane>>4)&1)*8 + (lane&7);
    int bcol = ((lane>>3)&1)*8;
    unsigned Abase = (unsigned)__cvta_generic_to_shared(As);
    unsigned Bbase = (unsigned)__cvta_generic_to_shared(Bs);
    unsigned a_lane = Abase + ((wm + arow)*AH + acol)*2;
    unsigned b_lane = Bbase + ((wn + brow)*AH + bcol)*2;

    float acc[4][4][4];
    #pragma unroll
    for(int i=0;i<4;i++)
        #pragma unroll
        for(int j=0;j<4;j++)
            #pragma unroll
            for(int r=0;r<4;r++) acc[i][j][r]=0.f;

    int lr = tid>>2;            // 0..63
    int lc = (tid&3)<<4;        // 0,16,32,48 halves
    const __half* Ag = A  + (size_t)(bm*128 + lr)*K + lc;
    const __half* Bg = Bw + (size_t)(bn*128 + lr)*K + lc;

    uint4 av[2][2], bv[2][2];
    #pragma unroll
    for(int r=0;r<2;r++)
        #pragma unroll
        for(int c=0;c<2;c++){
            av[r][c] = *(const uint4*)(Ag + (size_t)r*64*K + c*8);
            bv[r][c] = *(const uint4*)(Bg + (size_t)r*64*K + c*8);
        }

    for(int k0=0; k0<K; k0+=64){
        __syncthreads();
        #pragma unroll
        for(int r=0;r<2;r++)
            #pragma unroll
            for(int c=0;c<2;c++){
                *(uint4*)&As[(lr + r*64)*AH + lc + c*8] = av[r][c];
                *(uint4*)&Bs[(lr + r*64)*AH + lc + c*8] = bv[r][c];
            }
        __syncthreads();
        if (k0+64 < K){
            #pragma unroll
            for(int r=0;r<2;r++)
                #pragma unroll
                for(int c=0;c<2;c++){
                    av[r][c] = *(const uint4*)(Ag + k0+64 + (size_t)r*64*K + c*8);
                    bv[r][c] = *(const uint4*)(Bg + k0+64 + (size_t)r*64*K + c*8);
                }
        }
        #pragma unroll
        for(int ks=0;ks<4;ks++){
            unsigned af[4][4], bf[2][4];
            #pragma unroll
            for(int mi=0;mi<4;mi++)
                ldsm4(af[mi], a_lane + (mi*16*AH + ks*16)*2);
            #pragma unroll
            for(int p=0;p<2;p++)
                ldsm4(bf[p], b_lane + (p*16*AH + ks*16)*2);
            #pragma unroll
            for(int mi=0;mi<4;mi++)
                #pragma unroll
                for(int ni=0;ni<4;ni++)
                    mma16(acc[mi][ni], af[mi], &bf[ni>>1][(ni&1)*2]);
        }
    }

    #pragma unroll
    for(int mi=0;mi<4;mi++){
        #pragma unroll
        for(int ni=0;ni<4;ni++){
            int rowa = bm*128 + wm + mi*16 + g;
            int col  = bn*128 + wn + ni*8 + 2*t;
            if (mode == 0){
                *(float2*)(C + (size_t)rowa*N + col) =
                    make_float2(acc[mi][ni][0], acc[mi][ni][1]);
                *(float2*)(C + (size_t)(rowa+8)*N + col) =
                    make_float2(acc[mi][ni][2], acc[mi][ni][3]);
            } else {
                int h = col>>7, d = col&127;
                int b0_=rowa>>11, t0_=rowa&2047;
                *(float2*)(C + ((size_t)((b0_*NH+h)*T2+t0_))*HD + d) =
                    make_float2(acc[mi][ni][0], acc[mi][ni][1]);
                int m1 = rowa+8;
                int b1_=m1>>11, t1_=m1&2047;
                *(float2*)(C + ((size_t)((b1_*NH+h)*T2+t1_))*HD + d) =
                    make_float2(acc[mi][ni][2], acc[mi][ni][3]);
            }
        }
    }
}

// ---------------- RoPE: fp32 in -> fp16 out (scale folded) ----------------
__global__ void __launch_bounds__(256) rope_kernel(
    const float* __restrict__ in, __half* __restrict__ out, float scale)
{
    size_t idx = (size_t)blockIdx.x*256 + threadIdx.x;   // BH*T2*64 pairs
    int j  = (int)(idx & 63);
    int t  = (int)((idx >> 6) & 2047);
    int bh = (int)(idx >> 17);
    size_t base = ((size_t)bh*T2 + t)*HD;
    float x1 = in[base + j], x2 = in[base + j + 64];
    float invf = exp2f(-(float)j * (13.287712379549449f/64.0f));
    float ang  = (float)t * invf;
    float sn, cs; sincosf(ang, &sn, &cs);
    out[base + j]      = __float2half_rn((x1*cs - x2*sn)*scale);
    out[base + j + 64] = __float2half_rn((x1*sn + x2*cs)*scale);
}

// ---------------- V transpose: fp32 [BH][T][HD] -> fp16 [BH][HD][T] ----------
__global__ void __launch_bounds__(256) transposeTH_kernel(
    const float* __restrict__ in, __half* __restrict__ out)
{
    __shared__ float S[64][65];
    int t0 = blockIdx.x * 64;
    int d0 = blockIdx.y * 64;
    int bh = blockIdx.z;
    int tid = threadIdx.x;
    #pragma unroll
    for (int k=0;k<16;k++){
        int e = tid + k*256;
        int tl = e >> 6, dl = e & 63;
        S[tl][dl] = in[((size_t)bh*T2 + t0 + tl)*HD + d0 + dl];
    }
    __syncthreads();
    #pragma unroll
    for (int k=0;k<16;k++){
        int e = tid + k*256;
        int dl = e >> 6, tl = e & 63;
        out[((size_t)bh*HD + d0 + dl)*T2 + t0 + tl] = __float2half_rn(S[tl][dl]);
    }
}

// ---------------- fp16 flash attention (causal) ----------------
// Qh (pre-scaled), Kh: [BH][T][HD] fp16; Vt: [BH][HD][T] fp16.
// Output -> Y2 [BT][DIM] fp16. BM=128, BN=64, 8 warps x 16 rows.
#define QH 136
#define VH 72
#define PH 72
#define FL_HALF (128*QH + 64*QH + 128*VH + 128*PH)
#define FL_SMEM (FL_HALF*2)

__global__ void __launch_bounds__(256) flash3_kernel(
    const __half* __restrict__ Q, const __half* __restrict__ K,
    const __half* __restrict__ Vt, __half* __restrict__ Y2)
{
    extern __shared__ __align__(16) __half smh[];
    __half* Qs = smh;                // [128][136]
    __half* Ks = Qs + 128*QH;        // [64][136]
    __half* Vs = Ks + 64*QH;         // [128][72]  Vs[d][key]
    __half* Ps = Vs + 128*VH;        // [128][72]  Ps[m][key]

    int qb  = (int)(gridDim.x - 1 - blockIdx.x);
    int bh  = blockIdx.y;
    int tid = threadIdx.x;
    int warp = tid >> 5, lane = tid & 31;
    int g = lane >> 2, t = lane & 3;

    int arow = ((lane>>3)&1)*8 + (lane&7);
    int acol = (lane>>4)*8;
    int brow = ((lane>>4)&1)*8 + (lane&7);
    int bcol = ((lane>>3)&1)*8;
    unsigned Qbase = (unsigned)__cvta_generic_to_shared(Qs);
    unsigned Kbase = (unsigned)__cvta_generic_to_shared(Ks);
    unsigned Vbase = (unsigned)__cvta_generic_to_shared(Vs);
    unsigned Pbase = (unsigned)__cvta_generic_to_shared(Ps);
    unsigned q_lane = Qbase + ((warp*16 + arow)*QH + acol)*2;
    unsigned k_lane = Kbase + (brow*QH + bcol)*2;
    unsigned p_lane = Pbase + ((warp*16 + arow)*PH + acol)*2;
    unsigned v_lane = Vbase + (brow*VH + bcol)*2;

    // stage Q once
    const __half* qg = Q + ((size_t)bh*T2 + qb*128)*HD;
    #pragma unroll
    for (int it=0; it<8; it++){
        int idx = tid + it*256;
        int r = idx >> 4, c = (idx & 15) << 3;
        *(uint4*)&Qs[r*QH + c] = *(const uint4*)(qg + (size_t)r*HD + c);
    }

    float m0 = -1e30f, m1 = -1e30f, l0 = 0.f, l1 = 0.f;
    float o[16][4];
    #pragma unroll
    for (int i=0;i<16;i++)
        #pragma unroll
        for (int r=0;r<4;r++) o[i][r]=0.f;

    const __half* kg = K  + (size_t)bh*T2*HD;
    const __half* vg = Vt + (size_t)bh*HD*T2;
    int prow = warp*16 + g;
    int nkb = 2*qb + 2;

    for (int kb=0; kb<nkb; kb++){
        __syncthreads();
        #pragma unroll
        for (int it=0; it<4; it++){
            int idx = tid + it*256;
            int r = idx >> 4, c = (idx & 15) << 3;
            *(uint4*)&Ks[r*QH + c] = *(const uint4*)(kg + (size_t)(kb*64 + r)*HD + c);
        }
        #pragma unroll
        for (int it=0; it<4; it++){
            int idx = tid + it*256;
            int d = idx >> 3, c = (idx & 7) << 3;
            *(uint4*)&Vs[d*VH + c] = *(const uint4*)(vg + (size_t)d*T2 + kb*64 + c);
        }
        __syncthreads();

        // S = Q K^T : per warp 16 x 64, k=128 (8 k16-steps)
        float s[8][4];
        #pragma unroll
        for (int ni=0;ni<8;ni++)
            #pragma unroll
            for (int r=0;r<4;r++) s[ni][r]=0.f;
        #pragma unroll
        for (int ks=0; ks<8; ks++){
            unsigned af[4], kf[4][4];
            ldsm4(af, q_lane + ks*32);
            #pragma unroll
            for (int p=0;p<4;p++)
                ldsm4(kf[p], k_lane + (p*16*QH + ks*16)*2);
            #pragma unroll
            for (int ni=0;ni<8;ni++)
                mma16(s[ni], af, &kf[ni>>1][(ni&1)*2]);
        }

        // causal mask
        if (kb >= 2*qb){
            int q0 = qb*128 + prow, q1 = q0 + 8;
            #pragma unroll
            for (int ni=0;ni<8;ni++){
                int k0 = kb*64 + ni*8 + 2*t;
                if (k0   > q0) s[ni][0] = -1e30f;
                if (k0+1 > q0) s[ni][1] = -1e30f;
                if (k0   > q1) s[ni][2] = -1e30f;
                if (k0+1 > q1) s[ni][3] = -1e30f;
            }
        }

        // online softmax
        float mx0 = -1e30f, mx1 = -1e30f;
        #pragma unroll
        for (int ni=0;ni<8;ni++){
            mx0 = fmaxf(mx0, fmaxf(s[ni][0], s[ni][1]));
            mx1 = fmaxf(mx1, fmaxf(s[ni][2], s[ni][3]));
        }
        #pragma unroll
        for (int off=1; off<4; off<<=1){
            mx0 = fmaxf(mx0, __shfl_xor_sync(0xffffffffu, mx0, off, 4));
            mx1 = fmaxf(mx1, __shfl_xor_sync(0xffffffffu, mx1, off, 4));
        }
        float nm0 = fmaxf(m0, mx0), nm1 = fmaxf(m1, mx1);
        float a0 = __expf(m0 - nm0), a1 = __expf(m1 - nm1);
        m0 = nm0; m1 = nm1;
        float sum0 = 0.f, sum1 = 0.f;
        #pragma unroll
        for (int ni=0;ni<8;ni++){
            s[ni][0] = __expf(s[ni][0]-nm0); sum0 += s[ni][0];
            s[ni][1] = __expf(s[ni][1]-nm0); sum0 += s[ni][1];
            s[ni][2] = __expf(s[ni][2]-nm1); sum1 += s[ni][2];
            s[ni][3] = __expf(s[ni][3]-nm1); sum1 += s[ni][3];
        }
        #pragma unroll
        for (int off=1; off<4; off<<=1){
            sum0 += __shfl_xor_sync(0xffffffffu, sum0, off, 4);
            sum1 += __shfl_xor_sync(0xffffffffu, sum1, off, 4);
        }
        l0 = l0*a0 + sum0;
        l1 = l1*a1 + sum1;
        #pragma unroll
        for (int ti=0;ti<16;ti++){
            o[ti][0]*=a0; o[ti][1]*=a0; o[ti][2]*=a1; o[ti][3]*=a1;
        }

        // P -> smem (fp16)
        #pragma unroll
        for (int ni=0;ni<8;ni++){
            int cc = ni*8 + 2*t;
            *(__half2*)&Ps[prow*PH + cc]     = __floats2half2_rn(s[ni][0], s[ni][1]);
            *(__half2*)&Ps[(prow+8)*PH + cc] = __floats2half2_rn(s[ni][2], s[ni][3]);
        }
        __syncwarp();

        // O += P V : per warp 16 x 128, k=64 (4 k16-steps)
        #pragma unroll
        for (int ks=0; ks<4; ks++){
            unsigned af[4], vf[8][4];
            ldsm4(af, p_lane + ks*32);
            #pragma unroll
            for (int p=0;p<8;p++)
                ldsm4(vf[p], v_lane + (p*16*VH + ks*16)*2);
            #pragma unroll
            for (int ti=0;ti<16;ti++)
                mma16(o[ti], af, &vf[ti>>1][(ti&1)*2]);
        }
        __syncwarp();
    }

    // write to [BT][DIM] fp16
    float i0 = 1.0f/l0, i1 = 1.0f/l1;
    int trow = qb*128 + prow;
    int b_ = bh >> 4, h = bh & 15;
    __half* yr = Y2 + ((size_t)b_*T2)*DIM + h*HD;
    #pragma unroll
    for (int ti=0;ti<16;ti++){
        int col = ti*8 + 2*t;
        *(__half2*)(yr + (size_t)trow*DIM + col) =
            __floats2half2_rn(o[ti][0]*i0, o[ti][1]*i0);
        *(__half2*)(yr + (size_t)(trow+8)*DIM + col) =
            __floats2half2_rn(o[ti][2]*i1, o[ti][3]*i1);
    }
}

// ---------------- launch ----------------
extern "C" void kernel_launch(void* const* d_in, const int* in_sizes, int n_in,
                              void* d_out, int out_size)
{
    const float* x  = (const float*)d_in[0];
    const float* wq = (const float*)d_in[1];
    const float* wk = (const float*)d_in[2];
    const float* wv = (const float*)d_in[3];
    const float* wo = (const float*)d_in[4];
    float* out = (float*)d_out;

    __half *Wq,*Wk,*Wv,*Wo,*Xh,*Qh,*Kh,*Vt,*Y2;
    float *Qa,*Ka,*Vb;
    cudaGetSymbolAddress((void**)&Wq, g_Wq);
    cudaGetSymbolAddress((void**)&Wk, g_Wk);
    cudaGetSymbolAddress((void**)&Wv, g_Wv);
    cudaGetSymbolAddress((void**)&Wo, g_Wo);
    cudaGetSymbolAddress((void**)&Xh, g_Xh);
    cudaGetSymbolAddress((void**)&Qa, g_Qa);
    cudaGetSymbolAddress((void**)&Ka, g_Ka);
    cudaGetSymbolAddress((void**)&Vb, g_Vb);
    cudaGetSymbolAddress((void**)&Qh, g_Qh);
    cudaGetSymbolAddress((void**)&Kh, g_Kh);
    cudaGetSymbolAddress((void**)&Vt, g_Vt);
    cudaGetSymbolAddress((void**)&Y2, g_Y2);

    cudaFuncSetAttribute(flash3_kernel,
        cudaFuncAttributeMaxDynamicSharedMemorySize, FL_SMEM);

    dequant_kernel<<<DIM,256>>>(wq, Wq);
    dequant_kernel<<<DIM,256>>>(wk, Wk);
    dequant_kernel<<<DIM,256>>>(wv, Wv);
    dequant_kernel<<<DIM,256>>>(wo, Wo);
    tohalf_kernel<<<(BT*DIM)/2048, 256>>>(x, Xh);

    dim3 gg(DIM/128, BT/128);
    gemm_f16_kernel<<<gg,256>>>(Xh, Wq, Qa, BT, DIM, DIM, 1);
    gemm_f16_kernel<<<gg,256>>>(Xh, Wk, Ka, BT, DIM, DIM, 1);
    gemm_f16_kernel<<<gg,256>>>(Xh, Wv, Vb, BT, DIM, DIM, 1);

    rope_kernel<<<(BH*T2*64)/256, 256>>>(Qa, Qh, 0.08838834764831845f);
    rope_kernel<<<(BH*T2*64)/256, 256>>>(Ka, Kh, 1.0f);

    transposeTH_kernel<<<dim3(T2/64, HD/64, BH), 256>>>(Vb, Vt);

    flash3_kernel<<<dim3(T2/128, BH), 256, FL_SMEM>>>(Qh, Kh, Vt, Y2);

    gemm_f16_kernel<<<gg,256>>>(Y2, Wo, out, BT, DIM, DIM, 0);
}